// round 6
// baseline (speedup 1.0000x reference)
#include <cuda_runtime.h>
#include <cuda_fp16.h>
#include <math.h>
#include <stdint.h>

#define T_DIM 4096
#define H_DIM 1024
#define E_DIM 8
#define I_DIM 2048
#define STAGES 3

// ---------------- scratch (static device globals; zero-initialized) ----------------
__device__ __half g_w1h[(size_t)E_DIM * 2 * I_DIM * H_DIM];   // 67 MB
__device__ __half g_w2h[(size_t)E_DIM * H_DIM * I_DIM];       // 33.5 MB
__device__ __half g_normed_h[(size_t)T_DIM * H_DIM];          // 8 MB
__device__ __half g_act_h[(size_t)E_DIM * T_DIM * I_DIM];     // 134 MB
__device__ float  g_out2[(size_t)E_DIM * T_DIM * H_DIM];      // 134 MB
__device__ int    g_cnt[E_DIM];
__device__ int    g_tok[E_DIM * T_DIM];
__device__ int    g_slot[T_DIM * 2];
__device__ float  g_wgt[T_DIM * 2];

// ---------------- PTX helpers ----------------
__device__ __forceinline__ uint32_t smem_u32(const void* p) {
    uint32_t a;
    asm("{ .reg .u64 t; cvta.to.shared.u64 t, %1; cvt.u32.u64 %0, t; }" : "=r"(a) : "l"(p));
    return a;
}
__device__ __forceinline__ void cp16(uint32_t dst, const void* src) {
    asm volatile("cp.async.cg.shared.global [%0], [%1], 16;" :: "r"(dst), "l"(src));
}
#define CP_COMMIT() asm volatile("cp.async.commit_group;" ::: "memory")
#define CP_WAIT1()  asm volatile("cp.async.wait_group 1;" ::: "memory")
__device__ __forceinline__ void ldsm4(uint32_t* r, uint32_t addr) {
    asm volatile("ldmatrix.sync.aligned.m8n8.x4.shared.b16 {%0,%1,%2,%3}, [%4];"
        : "=r"(r[0]), "=r"(r[1]), "=r"(r[2]), "=r"(r[3]) : "r"(addr));
}
__device__ __forceinline__ void mma_f16(float* c, const uint32_t* a, const uint32_t* b) {
    asm("mma.sync.aligned.m16n8k16.row.col.f32.f16.f16.f32 "
        "{%0,%1,%2,%3},{%4,%5,%6,%7},{%8,%9},{%0,%1,%2,%3};"
        : "+f"(c[0]), "+f"(c[1]), "+f"(c[2]), "+f"(c[3])
        : "r"(a[0]), "r"(a[1]), "r"(a[2]), "r"(a[3]), "r"(b[0]), "r"(b[1]));
}
__device__ __forceinline__ float swiglu(float gv, float lv) {
    gv = fminf(gv, 7.f);
    lv = fminf(fmaxf(lv, -7.f), 7.f);
    const float sw = gv / (1.f + expf(-1.702f * gv));
    return sw * (lv + 1.f);
}

// ---------------- kernel: prep = zero counters + fp32->fp16 convert (w1 then w2) ----------------
__global__ __launch_bounds__(256) void k_prep(
    const float4* __restrict__ src1, uint2* __restrict__ dst1, int n1,
    const float4* __restrict__ src2, uint2* __restrict__ dst2, int n2)
{
    const int i = blockIdx.x * 256 + threadIdx.x;
    if (blockIdx.x == 0 && threadIdx.x < E_DIM) g_cnt[threadIdx.x] = 0;
    float4 v;
    uint2* d;
    if (i < n1) { v = src1[i]; d = dst1 + i; }
    else if (i < n1 + n2) { v = src2[i - n1]; d = dst2 + (i - n1); }
    else return;
    __half2 a = __floats2half2_rn(v.x, v.y);
    __half2 b = __floats2half2_rn(v.z, v.w);
    uint2 u;
    u.x = *(const uint32_t*)&a;
    u.y = *(const uint32_t*)&b;
    *d = u;
}

// ---------------- kernel 1: RMSNorm + gate + top-2 + routing ----------------
// 256 threads / token. Gate logits: warp w owns expert w (one 5-step shuffle per warp).
__global__ __launch_bounds__(256) void k_rms_gate(
    const float* __restrict__ x, const float* __restrict__ scale,
    const float* __restrict__ gk, const float* __restrict__ gb)
{
    const int t    = blockIdx.x;
    const int tid  = threadIdx.x;
    const int lane = tid & 31, wid = tid >> 5;

    __shared__ float  sred[8];
    __shared__ __half snorm[H_DIM];
    __shared__ float  slog[8];

    // ---- RMS sum of squares: warp shuffle + tiny smem combine ----
    const float4 xv = *(const float4*)(x + (size_t)t * H_DIM + tid * 4);
    float ss = xv.x * xv.x + xv.y * xv.y + xv.z * xv.z + xv.w * xv.w;
#pragma unroll
    for (int o = 16; o > 0; o >>= 1) ss += __shfl_xor_sync(0xffffffffu, ss, o);
    if (lane == 0) sred[wid] = ss;
    __syncthreads();
    float tot = sred[0] + sred[1] + sred[2] + sred[3]
              + sred[4] + sred[5] + sred[6] + sred[7];
    const float rinv = rsqrtf(tot * (1.0f / H_DIM) + 1e-5f);

    const float4 sc = *(const float4*)(scale + tid * 4);
    const float n0 = xv.x * rinv * sc.x;
    const float n1 = xv.y * rinv * sc.y;
    const float n2 = xv.z * rinv * sc.z;
    const float n3 = xv.w * rinv * sc.w;
    {
        __half2 a = __floats2half2_rn(n0, n1);
        __half2 b = __floats2half2_rn(n2, n3);
        uint2 u;
        u.x = *(const uint32_t*)&a;
        u.y = *(const uint32_t*)&b;
        *(uint2*)(g_normed_h + (size_t)t * H_DIM + tid * 4) = u;
        *(uint2*)(snorm + tid * 4) = u;
    }
    __syncthreads();

    // ---- gate logit for expert = wid ----
    const __half2* sn2 = (const __half2*)snorm;
    float acc = 0.f;
#pragma unroll
    for (int j = 0; j < 16; j++) {
        const int p = j * 32 + lane;            // half2 index; h = 2p
        const float2 f = __half22float2(sn2[p]);
        acc += f.x * __ldg(gk + (size_t)(2 * p) * E_DIM + wid)
             + f.y * __ldg(gk + (size_t)(2 * p + 1) * E_DIM + wid);
    }
#pragma unroll
    for (int o = 16; o > 0; o >>= 1) acc += __shfl_xor_sync(0xffffffffu, acc, o);
    if (lane == 0) slog[wid] = acc + gb[wid];
    __syncthreads();

    if (tid == 0) {
        int i0 = 0; float l0 = slog[0];
#pragma unroll
        for (int e = 1; e < E_DIM; e++) { if (slog[e] > l0) { l0 = slog[e]; i0 = e; } }
        int i1 = -1; float l1 = -3.4e38f;
#pragma unroll
        for (int e = 0; e < E_DIM; e++) {
            if (e != i0 && slog[e] > l1) { l1 = slog[e]; i1 = e; }
        }
        const float m  = fmaxf(l0, l1);
        const float e0 = expf(l0 - m), e1 = expf(l1 - m);
        const float inv = 1.0f / (e0 + e1);

        int p0 = atomicAdd(&g_cnt[i0], 1);
        int s0 = i0 * T_DIM + p0;
        g_tok[s0] = t; g_slot[2 * t + 0] = s0; g_wgt[2 * t + 0] = e0 * inv;
        int p1 = atomicAdd(&g_cnt[i1], 1);
        int s1 = i1 * T_DIM + p1;
        g_tok[s1] = t; g_slot[2 * t + 1] = s1; g_wgt[2 * t + 1] = e1 * inv;
    }
}

// ======================= GEMM kernels (fp16 mma + ldmatrix + cp.async) =======================
#define STAGE_BYTES 32768
#define G1_SMEM (1024 + STAGES * STAGE_BYTES)
#define G2_SMEM (1024 + STAGES * STAGE_BYTES)

// ---------------- kernel 2: grouped GEMM1 + SwiGLU -> g_act_h ----------------
__global__ __launch_bounds__(256) void k_gemm1(const float* __restrict__ b1)
{
    extern __shared__ char smem[];
    const int e  = blockIdx.z;
    const int ne = g_cnt[e];
    const int m0 = blockIdx.y * 128;
    if (m0 >= ne) return;
    const int n0 = blockIdx.x * 64;
    const int tid = threadIdx.x, lane = tid & 31, wid = tid >> 5;
    const int wm = wid >> 2, wn = wid & 3;
    const uint32_t sb = smem_u32(smem);

    int* stok = (int*)smem;
    if (tid < 128) {
        const int m = m0 + tid;
        stok[tid] = g_tok[e * T_DIM + (m < ne ? m : ne - 1)];
    }
    __syncthreads();

    const __half* w1g = g_w1h + ((size_t)e * 2 * I_DIM + n0) * H_DIM;
    const __half* w1l = w1g + (size_t)I_DIM * H_DIM;

    const int c8  = tid & 7;
    const int r32 = tid >> 3;
    const uint32_t swz = (uint32_t)((c8 ^ (r32 & 7)) << 4);
    const __half* asrc[4];
    const __half* bsrc[4];
    uint32_t adst[4], bdst[4];
#pragma unroll
    for (int i = 0; i < 4; i++) {
        const int row = r32 + i * 32;
        asrc[i] = g_normed_h + (size_t)stok[row] * H_DIM + c8 * 8;
        bsrc[i] = ((row < 64) ? (w1g + (size_t)row * H_DIM)
                              : (w1l + (size_t)(row - 64) * H_DIM)) + c8 * 8;
        adst[i] = sb + 1024u + (uint32_t)row * 128u + swz;
        bdst[i] = adst[i] + 16384u;
    }

#define G1_ISSUE(kt, s) do { \
    const uint32_t so = (uint32_t)(s) * STAGE_BYTES; \
    const int ko = (kt) * 64; \
    _Pragma("unroll") \
    for (int i = 0; i < 4; i++) { \
        cp16(adst[i] + so, asrc[i] + ko); \
        cp16(bdst[i] + so, bsrc[i] + ko); \
    } } while (0)

    const int NK = H_DIM / 64;   // 16
    G1_ISSUE(0, 0); CP_COMMIT();
    G1_ISSUE(1, 1); CP_COMMIT();

    float accg[4][2][4] = {}, accl[4][2][4] = {};

    const int lr  = lane & 7;
    const int rA  = ((lane >> 3) & 1) * 8 + lr;
    const int cA  = (lane >> 4);
    const int rB  = ((lane >> 4) & 1) * 8 + lr;
    const int cB  = ((lane >> 3) & 1);

    for (int c = 0; c < NK; c++) {
        CP_WAIT1();
        __syncthreads();
        if (c + 2 < NK) G1_ISSUE(c + 2, (c + 2) % STAGES);
        CP_COMMIT();

        const uint32_t Asm = sb + 1024u + (uint32_t)(c % STAGES) * STAGE_BYTES;
        const uint32_t Bsm = Asm + 16384u;
#pragma unroll
        for (int ks = 0; ks < 4; ks++) {
            uint32_t a[4][4];
            const uint32_t chA = (uint32_t)(((2 * ks + cA) ^ lr) << 4);
#pragma unroll
            for (int mf = 0; mf < 4; mf++) {
                const int row = wm * 64 + mf * 16 + rA;
                ldsm4(a[mf], Asm + (uint32_t)row * 128u + chA);
            }
            uint32_t bg[4], bl[4];
            const uint32_t chB = (uint32_t)(((2 * ks + cB) ^ lr) << 4);
            ldsm4(bg, Bsm + (uint32_t)(wn * 16 + rB) * 128u + chB);
            ldsm4(bl, Bsm + (uint32_t)(64 + wn * 16 + rB) * 128u + chB);
#pragma unroll
            for (int mf = 0; mf < 4; mf++) {
#pragma unroll
                for (int nf = 0; nf < 2; nf++) {
                    mma_f16(accg[mf][nf], a[mf], bg + 2 * nf);
                    mma_f16(accl[mf][nf], a[mf], bl + 2 * nf);
                }
            }
        }
    }

    const float* bgb = b1 + (size_t)e * 2 * I_DIM + n0;
    const float* blb = bgb + I_DIM;
#pragma unroll
    for (int mf = 0; mf < 4; mf++) {
        const int mb = m0 + wm * 64 + mf * 16 + (lane >> 2);
#pragma unroll
        for (int h = 0; h < 2; h++) {
            const int m = mb + h * 8;
            if (m < ne) {
                __half* orow = g_act_h + ((size_t)e * T_DIM + m) * I_DIM + n0;
#pragma unroll
                for (int nf = 0; nf < 2; nf++) {
                    const int nloc = wn * 16 + nf * 8 + 2 * (lane & 3);
                    const float g0 = accg[mf][nf][2 * h + 0] + bgb[nloc];
                    const float g1 = accg[mf][nf][2 * h + 1] + bgb[nloc + 1];
                    const float l0 = accl[mf][nf][2 * h + 0] + blb[nloc];
                    const float l1 = accl[mf][nf][2 * h + 1] + blb[nloc + 1];
                    __half2 o = __floats2half2_rn(swiglu(g0, l0), swiglu(g1, l1));
                    *(__half2*)(orow + nloc) = o;
                }
            }
        }
    }
#undef G1_ISSUE
}

// ---------------- kernel 3: grouped GEMM2 + bias -> g_out2 (fp32) ----------------
__global__ __launch_bounds__(256) void k_gemm2(const float* __restrict__ b2)
{
    extern __shared__ char smem[];
    const int e  = blockIdx.z;
    const int ne = g_cnt[e];
    const int m0 = blockIdx.y * 128;
    if (m0 >= ne) return;
    const int n0 = blockIdx.x * 128;
    const int tid = threadIdx.x, lane = tid & 31, wid = tid >> 5;
    const int wm = wid >> 2, wn = wid & 3;
    const uint32_t sb = smem_u32(smem);

    const __half* a_base = g_act_h + ((size_t)e * T_DIM + m0) * I_DIM;
    const __half* b_base = g_w2h + ((size_t)e * H_DIM + n0) * I_DIM;

    const int c8  = tid & 7;
    const int r32 = tid >> 3;
    const uint32_t swz = (uint32_t)((c8 ^ (r32 & 7)) << 4);
    const __half* asrc[4];
    const __half* bsrc[4];
    uint32_t adst[4], bdst[4];
#pragma unroll
    for (int i = 0; i < 4; i++) {
        const int row = r32 + i * 32;
        asrc[i] = a_base + (size_t)row * I_DIM + c8 * 8;
        bsrc[i] = b_base + (size_t)row * I_DIM + c8 * 8;
        adst[i] = sb + 1024u + (uint32_t)row * 128u + swz;
        bdst[i] = adst[i] + 16384u;
    }

#define G2_ISSUE(kt, s) do { \
    const uint32_t so = (uint32_t)(s) * STAGE_BYTES; \
    const int ko = (kt) * 64; \
    _Pragma("unroll") \
    for (int i = 0; i < 4; i++) { \
        cp16(adst[i] + so, asrc[i] + ko); \
        cp16(bdst[i] + so, bsrc[i] + ko); \
    } } while (0)

    const int NK = I_DIM / 64;   // 32
    G2_ISSUE(0, 0); CP_COMMIT();
    G2_ISSUE(1, 1); CP_COMMIT();

    float acc[4][4][4] = {};

    const int lr  = lane & 7;
    const int rA  = ((lane >> 3) & 1) * 8 + lr;
    const int cA  = (lane >> 4);
    const int rB  = ((lane >> 4) & 1) * 8 + lr;
    const int cB  = ((lane >> 3) & 1);

    for (int c = 0; c < NK; c++) {
        CP_WAIT1();
        __syncthreads();
        if (c + 2 < NK) G2_ISSUE(c + 2, (c + 2) % STAGES);
        CP_COMMIT();

        const uint32_t Asm = sb + 1024u + (uint32_t)(c % STAGES) * STAGE_BYTES;
        const uint32_t Bsm = Asm + 16384u;
#pragma unroll
        for (int ks = 0; ks < 4; ks++) {
            uint32_t a[4][4];
            const uint32_t chA = (uint32_t)(((2 * ks + cA) ^ lr) << 4);
#pragma unroll
            for (int mf = 0; mf < 4; mf++) {
                const int row = wm * 64 + mf * 16 + rA;
                ldsm4(a[mf], Asm + (uint32_t)row * 128u + chA);
            }
            uint32_t b[2][4];
            const uint32_t chB = (uint32_t)(((2 * ks + cB) ^ lr) << 4);
            ldsm4(b[0], Bsm + (uint32_t)(wn * 32 + rB) * 128u + chB);
            ldsm4(b[1], Bsm + (uint32_t)(wn * 32 + 16 + rB) * 128u + chB);
#pragma unroll
            for (int mf = 0; mf < 4; mf++) {
#pragma unroll
                for (int nf = 0; nf < 4; nf++)
                    mma_f16(acc[mf][nf], a[mf], b[nf >> 1] + 2 * (nf & 1));
            }
        }
    }

    const float* bb = b2 + (size_t)e * H_DIM + n0;
#pragma unroll
    for (int mf = 0; mf < 4; mf++) {
        const int mb = m0 + wm * 64 + mf * 16 + (lane >> 2);
#pragma unroll
        for (int h = 0; h < 2; h++) {
            const int m = mb + h * 8;
            if (m < ne) {
                float* orow = g_out2 + ((size_t)e * T_DIM + m) * H_DIM + n0;
#pragma unroll
                for (int nf = 0; nf < 4; nf++) {
                    const int nloc = wn * 32 + nf * 8 + 2 * (lane & 3);
                    float2 o = { acc[mf][nf][2 * h + 0] + bb[nloc],
                                 acc[mf][nf][2 * h + 1] + bb[nloc + 1] };
                    *(float2*)(orow + nloc) = o;
                }
            }
        }
    }
#undef G2_ISSUE
}

// ---------------- kernel 4: gather-combine + residual ----------------
__global__ __launch_bounds__(256) void k_combine(
    const float* __restrict__ x, float* __restrict__ out)
{
    const size_t idx = (size_t)blockIdx.x * blockDim.x + threadIdx.x;
    if (idx >= (size_t)T_DIM * H_DIM / 4) return;
    const int t  = (int)(idx / (H_DIM / 4));
    const int hc = (int)(idx % (H_DIM / 4));

    const int   s0 = g_slot[2 * t + 0], s1 = g_slot[2 * t + 1];
    const float w0 = g_wgt[2 * t + 0],  w1 = g_wgt[2 * t + 1];

    const float4 xv = ((const float4*)x)[idx];
    const float4 o0 = *(const float4*)(g_out2 + (size_t)s0 * H_DIM + hc * 4);
    const float4 o1 = *(const float4*)(g_out2 + (size_t)s1 * H_DIM + hc * 4);
    float4 o;
    o.x = xv.x + w0 * o0.x + w1 * o1.x;
    o.y = xv.y + w0 * o0.y + w1 * o1.y;
    o.z = xv.z + w0 * o0.z + w1 * o1.z;
    o.w = xv.w + w0 * o0.w + w1 * o1.w;
    ((float4*)out)[idx] = o;
}

// ---------------- launch ----------------
extern "C" void kernel_launch(void* const* d_in, const int* in_sizes, int n_in,
                              void* d_out, int out_size)
{
    const float* x     = (const float*)d_in[0];
    const float* scale = (const float*)d_in[1];
    const float* gk    = (const float*)d_in[2];
    const float* gb    = (const float*)d_in[3];
    const float* w1    = (const float*)d_in[4];
    const float* b1    = (const float*)d_in[5];
    const float* w2    = (const float*)d_in[6];
    const float* b2    = (const float*)d_in[7];
    float* out = (float*)d_out;

    cudaFuncSetAttribute(k_gemm1, cudaFuncAttributeMaxDynamicSharedMemorySize, G1_SMEM);
    cudaFuncSetAttribute(k_gemm2, cudaFuncAttributeMaxDynamicSharedMemorySize, G2_SMEM);

    __half* w1h_p; cudaGetSymbolAddress((void**)&w1h_p, g_w1h);
    __half* w2h_p; cudaGetSymbolAddress((void**)&w2h_p, g_w2h);
    const int n4_1 = E_DIM * 2 * I_DIM * H_DIM / 4;   // 8.39M float4
    const int n4_2 = E_DIM * H_DIM * I_DIM / 4;       // 4.19M float4
    const int nprep = n4_1 + n4_2;
    k_prep<<<(nprep + 255) / 256, 256>>>((const float4*)w1, (uint2*)w1h_p, n4_1,
                                         (const float4*)w2, (uint2*)w2h_p, n4_2);

    k_rms_gate<<<T_DIM, 256>>>(x, scale, gk, gb);

    dim3 g1(I_DIM / 64, T_DIM / 128, E_DIM);    // 32 x 32 x 8
    k_gemm1<<<g1, 256, G1_SMEM>>>(b1);

    dim3 g2(H_DIM / 128, T_DIM / 128, E_DIM);   // 8 x 32 x 8
    k_gemm2<<<g2, 256, G2_SMEM>>>(b2);

    k_combine<<<(T_DIM * H_DIM / 4 + 255) / 256, 256>>>(x, out);
}

// round 7
// speedup vs baseline: 1.0586x; 1.0586x over previous
#include <cuda_runtime.h>
#include <cuda_fp16.h>
#include <math.h>
#include <stdint.h>

#define T_DIM 4096
#define H_DIM 1024
#define E_DIM 8
#define I_DIM 2048
#define STAGES 3

// ---------------- scratch (static device globals; zero-initialized) ----------------
__device__ __half g_w1h[(size_t)E_DIM * 2 * I_DIM * H_DIM];   // 67 MB
__device__ __half g_w2h[(size_t)E_DIM * H_DIM * I_DIM];       // 33.5 MB
__device__ __half g_normed_h[(size_t)T_DIM * H_DIM];          // 8 MB
__device__ __half g_act_h[(size_t)E_DIM * T_DIM * I_DIM];     // 134 MB
__device__ float  g_out2[(size_t)E_DIM * T_DIM * H_DIM];      // 134 MB
__device__ int    g_cnt[E_DIM];
__device__ int    g_tok[E_DIM * T_DIM];
__device__ int    g_slot[T_DIM * 2];
__device__ float  g_wgt[T_DIM * 2];

// ---------------- PTX helpers ----------------
__device__ __forceinline__ uint32_t smem_u32(const void* p) {
    uint32_t a;
    asm("{ .reg .u64 t; cvta.to.shared.u64 t, %1; cvt.u32.u64 %0, t; }" : "=r"(a) : "l"(p));
    return a;
}
__device__ __forceinline__ void cp16(uint32_t dst, const void* src) {
    asm volatile("cp.async.cg.shared.global [%0], [%1], 16;" :: "r"(dst), "l"(src));
}
#define CP_COMMIT() asm volatile("cp.async.commit_group;" ::: "memory")
#define CP_WAIT1()  asm volatile("cp.async.wait_group 1;" ::: "memory")
__device__ __forceinline__ void ldsm4(uint32_t* r, uint32_t addr) {
    asm volatile("ldmatrix.sync.aligned.m8n8.x4.shared.b16 {%0,%1,%2,%3}, [%4];"
        : "=r"(r[0]), "=r"(r[1]), "=r"(r[2]), "=r"(r[3]) : "r"(addr));
}
__device__ __forceinline__ void mma_f16(float* c, const uint32_t* a, const uint32_t* b) {
    asm("mma.sync.aligned.m16n8k16.row.col.f32.f16.f16.f32 "
        "{%0,%1,%2,%3},{%4,%5,%6,%7},{%8,%9},{%0,%1,%2,%3};"
        : "+f"(c[0]), "+f"(c[1]), "+f"(c[2]), "+f"(c[3])
        : "r"(a[0]), "r"(a[1]), "r"(a[2]), "r"(a[3]), "r"(b[0]), "r"(b[1]));
}
__device__ __forceinline__ float swiglu(float gv, float lv) {
    gv = fminf(gv, 7.f);
    lv = fminf(fmaxf(lv, -7.f), 7.f);
    const float sw = gv / (1.f + expf(-1.702f * gv));
    return sw * (lv + 1.f);
}

// ---------------- kernel: fp32 -> fp16 conversion ----------------
__global__ __launch_bounds__(256) void k_cvt(const float4* __restrict__ src,
                                             uint2* __restrict__ dst, int n4)
{
    const int i = blockIdx.x * 256 + threadIdx.x;
    if (i < n4) {
        const float4 v = src[i];
        __half2 a = __floats2half2_rn(v.x, v.y);
        __half2 b = __floats2half2_rn(v.z, v.w);
        uint2 u;
        u.x = *(const uint32_t*)&a;
        u.y = *(const uint32_t*)&b;
        dst[i] = u;
    }
}

// ---------------- kernel 0: reset routing counters ----------------
__global__ void k_zero() {
    if (threadIdx.x < E_DIM) g_cnt[threadIdx.x] = 0;
}

// ---------------- kernel 1: RMSNorm + gate + top-2 + routing ----------------
// 256 threads / token. Gate logits computed in fp32 from SMEM-staged fp32 normed:
// warp w owns expert w (one 5-step shuffle per warp instead of 40 shuffles/thread).
__global__ __launch_bounds__(256) void k_rms_gate(
    const float* __restrict__ x, const float* __restrict__ scale,
    const float* __restrict__ gk, const float* __restrict__ gb)
{
    const int t    = blockIdx.x;
    const int tid  = threadIdx.x;
    const int lane = tid & 31, wid = tid >> 5;

    __shared__ float sred[8];
    __shared__ float snorm[H_DIM];    // fp32 normed for gating precision
    __shared__ float slog[8];

    const float4 xv = *(const float4*)(x + (size_t)t * H_DIM + tid * 4);
    float ss = xv.x * xv.x + xv.y * xv.y + xv.z * xv.z + xv.w * xv.w;
#pragma unroll
    for (int o = 16; o > 0; o >>= 1) ss += __shfl_xor_sync(0xffffffffu, ss, o);
    if (lane == 0) sred[wid] = ss;
    __syncthreads();
    float tot = sred[0] + sred[1] + sred[2] + sred[3]
              + sred[4] + sred[5] + sred[6] + sred[7];
    const float rinv = rsqrtf(tot * (1.0f / H_DIM) + 1e-5f);

    const float4 sc = *(const float4*)(scale + tid * 4);
    float4 nv;
    nv.x = xv.x * rinv * sc.x;
    nv.y = xv.y * rinv * sc.y;
    nv.z = xv.z * rinv * sc.z;
    nv.w = xv.w * rinv * sc.w;
    *(float4*)(snorm + tid * 4) = nv;
    {
        __half2 a = __floats2half2_rn(nv.x, nv.y);
        __half2 b = __floats2half2_rn(nv.z, nv.w);
        uint2 u;
        u.x = *(const uint32_t*)&a;
        u.y = *(const uint32_t*)&b;
        *(uint2*)(g_normed_h + (size_t)t * H_DIM + tid * 4) = u;
    }
    __syncthreads();

    // ---- gate logit for expert = wid (fp32) ----
    float acc = 0.f;
#pragma unroll
    for (int j = 0; j < 32; j++) {
        const int h = j * 32 + lane;
        acc += snorm[h] * __ldg(gk + (size_t)h * E_DIM + wid);
    }
#pragma unroll
    for (int o = 16; o > 0; o >>= 1) acc += __shfl_xor_sync(0xffffffffu, acc, o);
    if (lane == 0) slog[wid] = acc + gb[wid];
    __syncthreads();

    if (tid == 0) {
        int i0 = 0; float l0 = slog[0];
#pragma unroll
        for (int e = 1; e < E_DIM; e++) { if (slog[e] > l0) { l0 = slog[e]; i0 = e; } }
        int i1 = -1; float l1 = -3.4e38f;
#pragma unroll
        for (int e = 0; e < E_DIM; e++) {
            if (e != i0 && slog[e] > l1) { l1 = slog[e]; i1 = e; }
        }
        const float m  = fmaxf(l0, l1);
        const float e0 = expf(l0 - m), e1 = expf(l1 - m);
        const float inv = 1.0f / (e0 + e1);

        int p0 = atomicAdd(&g_cnt[i0], 1);
        int s0 = i0 * T_DIM + p0;
        g_tok[s0] = t; g_slot[2 * t + 0] = s0; g_wgt[2 * t + 0] = e0 * inv;
        int p1 = atomicAdd(&g_cnt[i1], 1);
        int s1 = i1 * T_DIM + p1;
        g_tok[s1] = t; g_slot[2 * t + 1] = s1; g_wgt[2 * t + 1] = e1 * inv;
    }
}

// ======================= GEMM kernels (fp16 mma + ldmatrix + cp.async) =======================
#define STAGE_BYTES 32768
#define G1_SMEM (1024 + STAGES * STAGE_BYTES)
#define G2_SMEM (1024 + STAGES * STAGE_BYTES)

// ---------------- kernel 2: grouped GEMM1 + SwiGLU -> g_act_h ----------------
__global__ __launch_bounds__(256, 2) void k_gemm1(const float* __restrict__ b1)
{
    extern __shared__ char smem[];
    const int e  = blockIdx.z;
    const int ne = g_cnt[e];
    const int m0 = blockIdx.y * 128;
    if (m0 >= ne) return;
    const int n0 = blockIdx.x * 64;
    const int tid = threadIdx.x, lane = tid & 31, wid = tid >> 5;
    const int wm = wid >> 2, wn = wid & 3;
    const uint32_t sb = smem_u32(smem);

    int* stok = (int*)smem;
    if (tid < 128) {
        const int m = m0 + tid;
        stok[tid] = g_tok[e * T_DIM + (m < ne ? m : ne - 1)];
    }
    __syncthreads();

    const __half* w1g = g_w1h + ((size_t)e * 2 * I_DIM + n0) * H_DIM;
    const __half* w1l = w1g + (size_t)I_DIM * H_DIM;

    const int c8  = tid & 7;
    const int r32 = tid >> 3;
    const uint32_t swz = (uint32_t)((c8 ^ (r32 & 7)) << 4);
    const __half* asrc[4];
    const __half* bsrc[4];
    uint32_t adst[4], bdst[4];
#pragma unroll
    for (int i = 0; i < 4; i++) {
        const int row = r32 + i * 32;
        asrc[i] = g_normed_h + (size_t)stok[row] * H_DIM + c8 * 8;
        bsrc[i] = ((row < 64) ? (w1g + (size_t)row * H_DIM)
                              : (w1l + (size_t)(row - 64) * H_DIM)) + c8 * 8;
        adst[i] = sb + 1024u + (uint32_t)row * 128u + swz;
        bdst[i] = adst[i] + 16384u;
    }

#define G1_ISSUE(kt, s) do { \
    const uint32_t so = (uint32_t)(s) * STAGE_BYTES; \
    const int ko = (kt) * 64; \
    _Pragma("unroll") \
    for (int i = 0; i < 4; i++) { \
        cp16(adst[i] + so, asrc[i] + ko); \
        cp16(bdst[i] + so, bsrc[i] + ko); \
    } } while (0)

    const int NK = H_DIM / 64;   // 16
    G1_ISSUE(0, 0); CP_COMMIT();
    G1_ISSUE(1, 1); CP_COMMIT();

    float accg[4][2][4] = {}, accl[4][2][4] = {};

    const int lr  = lane & 7;
    const int rA  = ((lane >> 3) & 1) * 8 + lr;
    const int cA  = (lane >> 4);
    const int rB  = ((lane >> 4) & 1) * 8 + lr;
    const int cB  = ((lane >> 3) & 1);

    for (int c = 0; c < NK; c++) {
        CP_WAIT1();
        __syncthreads();
        if (c + 2 < NK) G1_ISSUE(c + 2, (c + 2) % STAGES);
        CP_COMMIT();

        const uint32_t Asm = sb + 1024u + (uint32_t)(c % STAGES) * STAGE_BYTES;
        const uint32_t Bsm = Asm + 16384u;
#pragma unroll
        for (int ks = 0; ks < 4; ks++) {
            uint32_t a[4][4];
            const uint32_t chA = (uint32_t)(((2 * ks + cA) ^ lr) << 4);
#pragma unroll
            for (int mf = 0; mf < 4; mf++) {
                const int row = wm * 64 + mf * 16 + rA;
                ldsm4(a[mf], Asm + (uint32_t)row * 128u + chA);
            }
            uint32_t bg[4], bl[4];
            const uint32_t chB = (uint32_t)(((2 * ks + cB) ^ lr) << 4);
            ldsm4(bg, Bsm + (uint32_t)(wn * 16 + rB) * 128u + chB);
            ldsm4(bl, Bsm + (uint32_t)(64 + wn * 16 + rB) * 128u + chB);
#pragma unroll
            for (int mf = 0; mf < 4; mf++) {
#pragma unroll
                for (int nf = 0; nf < 2; nf++) {
                    mma_f16(accg[mf][nf], a[mf], bg + 2 * nf);
                    mma_f16(accl[mf][nf], a[mf], bl + 2 * nf);
                }
            }
        }
    }

    const float* bgb = b1 + (size_t)e * 2 * I_DIM + n0;
    const float* blb = bgb + I_DIM;
#pragma unroll
    for (int mf = 0; mf < 4; mf++) {
        const int mb = m0 + wm * 64 + mf * 16 + (lane >> 2);
#pragma unroll
        for (int h = 0; h < 2; h++) {
            const int m = mb + h * 8;
            if (m < ne) {
                __half* orow = g_act_h + ((size_t)e * T_DIM + m) * I_DIM + n0;
#pragma unroll
                for (int nf = 0; nf < 2; nf++) {
                    const int nloc = wn * 16 + nf * 8 + 2 * (lane & 3);
                    const float g0 = accg[mf][nf][2 * h + 0] + bgb[nloc];
                    const float g1 = accg[mf][nf][2 * h + 1] + bgb[nloc + 1];
                    const float l0 = accl[mf][nf][2 * h + 0] + blb[nloc];
                    const float l1 = accl[mf][nf][2 * h + 1] + blb[nloc + 1];
                    __half2 o = __floats2half2_rn(swiglu(g0, l0), swiglu(g1, l1));
                    *(__half2*)(orow + nloc) = o;
                }
            }
        }
    }
#undef G1_ISSUE
}

// ---------------- kernel 3: grouped GEMM2 + bias -> g_out2 (fp32) ----------------
__global__ __launch_bounds__(256, 2) void k_gemm2(const float* __restrict__ b2)
{
    extern __shared__ char smem[];
    const int e  = blockIdx.z;
    const int ne = g_cnt[e];
    const int m0 = blockIdx.y * 128;
    if (m0 >= ne) return;
    const int n0 = blockIdx.x * 128;
    const int tid = threadIdx.x, lane = tid & 31, wid = tid >> 5;
    const int wm = wid >> 2, wn = wid & 3;
    const uint32_t sb = smem_u32(smem);

    const __half* a_base = g_act_h + ((size_t)e * T_DIM + m0) * I_DIM;
    const __half* b_base = g_w2h + ((size_t)e * H_DIM + n0) * I_DIM;

    const int c8  = tid & 7;
    const int r32 = tid >> 3;
    const uint32_t swz = (uint32_t)((c8 ^ (r32 & 7)) << 4);
    const __half* asrc[4];
    const __half* bsrc[4];
    uint32_t adst[4], bdst[4];
#pragma unroll
    for (int i = 0; i < 4; i++) {
        const int row = r32 + i * 32;
        asrc[i] = a_base + (size_t)row * I_DIM + c8 * 8;
        bsrc[i] = b_base + (size_t)row * I_DIM + c8 * 8;
        adst[i] = sb + 1024u + (uint32_t)row * 128u + swz;
        bdst[i] = adst[i] + 16384u;
    }

#define G2_ISSUE(kt, s) do { \
    const uint32_t so = (uint32_t)(s) * STAGE_BYTES; \
    const int ko = (kt) * 64; \
    _Pragma("unroll") \
    for (int i = 0; i < 4; i++) { \
        cp16(adst[i] + so, asrc[i] + ko); \
        cp16(bdst[i] + so, bsrc[i] + ko); \
    } } while (0)

    const int NK = I_DIM / 64;   // 32
    G2_ISSUE(0, 0); CP_COMMIT();
    G2_ISSUE(1, 1); CP_COMMIT();

    float acc[4][4][4] = {};

    const int lr  = lane & 7;
    const int rA  = ((lane >> 3) & 1) * 8 + lr;
    const int cA  = (lane >> 4);
    const int rB  = ((lane >> 4) & 1) * 8 + lr;
    const int cB  = ((lane >> 3) & 1);

    for (int c = 0; c < NK; c++) {
        CP_WAIT1();
        __syncthreads();
        if (c + 2 < NK) G2_ISSUE(c + 2, (c + 2) % STAGES);
        CP_COMMIT();

        const uint32_t Asm = sb + 1024u + (uint32_t)(c % STAGES) * STAGE_BYTES;
        const uint32_t Bsm = Asm + 16384u;
#pragma unroll
        for (int ks = 0; ks < 4; ks++) {
            uint32_t a[4][4];
            const uint32_t chA = (uint32_t)(((2 * ks + cA) ^ lr) << 4);
#pragma unroll
            for (int mf = 0; mf < 4; mf++) {
                const int row = wm * 64 + mf * 16 + rA;
                ldsm4(a[mf], Asm + (uint32_t)row * 128u + chA);
            }
            uint32_t b[2][4];
            const uint32_t chB = (uint32_t)(((2 * ks + cB) ^ lr) << 4);
            ldsm4(b[0], Bsm + (uint32_t)(wn * 32 + rB) * 128u + chB);
            ldsm4(b[1], Bsm + (uint32_t)(wn * 32 + 16 + rB) * 128u + chB);
#pragma unroll
            for (int mf = 0; mf < 4; mf++) {
#pragma unroll
                for (int nf = 0; nf < 4; nf++)
                    mma_f16(acc[mf][nf], a[mf], b[nf >> 1] + 2 * (nf & 1));
            }
        }
    }

    const float* bb = b2 + (size_t)e * H_DIM + n0;
#pragma unroll
    for (int mf = 0; mf < 4; mf++) {
        const int mb = m0 + wm * 64 + mf * 16 + (lane >> 2);
#pragma unroll
        for (int h = 0; h < 2; h++) {
            const int m = mb + h * 8;
            if (m < ne) {
                float* orow = g_out2 + ((size_t)e * T_DIM + m) * H_DIM + n0;
#pragma unroll
                for (int nf = 0; nf < 4; nf++) {
                    const int nloc = wn * 32 + nf * 8 + 2 * (lane & 3);
                    float2 o = { acc[mf][nf][2 * h + 0] + bb[nloc],
                                 acc[mf][nf][2 * h + 1] + bb[nloc + 1] };
                    *(float2*)(orow + nloc) = o;
                }
            }
        }
    }
#undef G2_ISSUE
}

// ---------------- kernel 4: gather-combine + residual ----------------
__global__ __launch_bounds__(256) void k_combine(
    const float* __restrict__ x, float* __restrict__ out)
{
    const size_t idx = (size_t)blockIdx.x * blockDim.x + threadIdx.x;
    if (idx >= (size_t)T_DIM * H_DIM / 4) return;
    const int t  = (int)(idx / (H_DIM / 4));
    const int hc = (int)(idx % (H_DIM / 4));

    const int   s0 = g_slot[2 * t + 0], s1 = g_slot[2 * t + 1];
    const float w0 = g_wgt[2 * t + 0],  w1 = g_wgt[2 * t + 1];

    const float4 xv = ((const float4*)x)[idx];
    const float4 o0 = *(const float4*)(g_out2 + (size_t)s0 * H_DIM + hc * 4);
    const float4 o1 = *(const float4*)(g_out2 + (size_t)s1 * H_DIM + hc * 4);
    float4 o;
    o.x = xv.x + w0 * o0.x + w1 * o1.x;
    o.y = xv.y + w0 * o0.y + w1 * o1.y;
    o.z = xv.z + w0 * o0.z + w1 * o1.z;
    o.w = xv.w + w0 * o0.w + w1 * o1.w;
    ((float4*)out)[idx] = o;
}

// ---------------- launch ----------------
extern "C" void kernel_launch(void* const* d_in, const int* in_sizes, int n_in,
                              void* d_out, int out_size)
{
    const float* x     = (const float*)d_in[0];
    const float* scale = (const float*)d_in[1];
    const float* gk    = (const float*)d_in[2];
    const float* gb    = (const float*)d_in[3];
    const float* w1    = (const float*)d_in[4];
    const float* b1    = (const float*)d_in[5];
    const float* w2    = (const float*)d_in[6];
    const float* b2    = (const float*)d_in[7];
    float* out = (float*)d_out;

    cudaFuncSetAttribute(k_gemm1, cudaFuncAttributeMaxDynamicSharedMemorySize, G1_SMEM);
    cudaFuncSetAttribute(k_gemm2, cudaFuncAttributeMaxDynamicSharedMemorySize, G2_SMEM);

    k_zero<<<1, 32>>>();

    {
        __half* w1h_p; cudaGetSymbolAddress((void**)&w1h_p, g_w1h);
        __half* w2h_p; cudaGetSymbolAddress((void**)&w2h_p, g_w2h);
        const int n4_1 = E_DIM * 2 * I_DIM * H_DIM / 4;
        const int n4_2 = E_DIM * H_DIM * I_DIM / 4;
        k_cvt<<<n4_1 / 256, 256>>>((const float4*)w1, (uint2*)w1h_p, n4_1);
        k_cvt<<<n4_2 / 256, 256>>>((const float4*)w2, (uint2*)w2h_p, n4_2);
    }

    k_rms_gate<<<T_DIM, 256>>>(x, scale, gk, gb);

    dim3 g1(I_DIM / 64, T_DIM / 128, E_DIM);    // 32 x 32 x 8
    k_gemm1<<<g1, 256, G1_SMEM>>>(b1);

    dim3 g2(H_DIM / 128, T_DIM / 128, E_DIM);   // 8 x 32 x 8
    k_gemm2<<<g2, 256, G2_SMEM>>>(b2);

    k_combine<<<(T_DIM * H_DIM / 4 + 255) / 256, 256>>>(x, out);
}